// round 7
// baseline (speedup 1.0000x reference)
#include <cuda_runtime.h>
#include <cuda_fp16.h>
#include <cstdint>
#include <math.h>

// ---------------- problem constants ----------------
#define NS   5760
#define CO   640
#define KD   192
#define NPOS 16
#define B_   8
#define WAY_ 5
#define NQ_  75
#define P_   9
#define NTOT (NS * NPOS)     // 92160
#define KE2  576             // 3 * 192 fp16-split K
#define TNB  64              // N per block = 4 images
#define KC   48              // K halves per chunk
#define NCH  12              // 576 / 48

// ---------------- device scratch ----------------
__device__ __align__(128) __half g_X[(size_t)NTOT * KE2];  // 106 MB
__device__ __align__(128) __half g_W[(size_t)CO * KE2];    // 737 KB
__device__ float g_u[(size_t)NS * CO];

__device__ __forceinline__ uint32_t smem_u32(const void* p) {
    uint32_t a;
    asm("{ .reg .u64 t; cvta.to.shared.u64 t, %1; cvt.u32.u64 %0, t; }"
        : "=r"(a) : "l"(p));
    return a;
}

// ---------------------------------------------------------------------------
// Prep W: fp16 split, K-concat [w0 | w0 | w1]
// ---------------------------------------------------------------------------
__global__ void k_prepw(const float* __restrict__ w) {
    int i = blockIdx.x * 256 + threadIdx.x;
    if (i >= CO * KD) return;
    int ch = i / KD, k = i % KD;
    float v = w[i];
    __half h0 = __float2half_rn(v);
    __half h1 = __float2half_rn(v - __half2float(h0));
    size_t b = (size_t)ch * KE2;
    g_W[b + k]       = h0;
    g_W[b + 192 + k] = h0;
    g_W[b + 384 + k] = h1;
}

// ---------------------------------------------------------------------------
// Prep X: im2col + fp16 split, K-concat [x0 | x1 | x0]. One block per image.
// ---------------------------------------------------------------------------
__global__ void __launch_bounds__(128) k_prepx(const float* __restrict__ data) {
    __shared__ __align__(16) __half xsm[NPOS * KE2];   // 18 KB
    const int s = blockIdx.x, t = threadIdx.x;
    const float* img = data + (size_t)s * 3072;
    for (int i = t; i < 3072; i += 128) {
        float v = img[i];
        int ci = i >> 10, row = (i >> 5) & 31, col = i & 31;
        int k   = ci * 64 + (row & 7) * 8 + (col & 7);
        int pos = (row >> 3) * 4 + (col >> 3);
        __half h0 = __float2half_rn(v);
        __half h1 = __float2half_rn(v - __half2float(h0));
        int r = pos * KE2;
        xsm[r + k]       = h0;
        xsm[r + 192 + k] = h1;
        xsm[r + 384 + k] = h0;
    }
    __syncthreads();
    uint4* dst = reinterpret_cast<uint4*>(g_X + (size_t)s * NPOS * KE2);
    const uint4* src = reinterpret_cast<const uint4*>(xsm);
    for (int g = t; g < NPOS * KE2 / 8; g += 128) dst[g] = src[g];
}

// ---------------------------------------------------------------------------
// Fused GEMM + norms. 12 chunks of KC=48, double-buffered A, one sync/chunk.
// ---------------------------------------------------------------------------
#define BST     584                       // B row stride (halves): 1168 B
#define AST     56                        // A row stride (halves): 112 B
#define OFF_B   0
#define BSZ     (64 * BST * 2)            // 74752
#define OFF_A   BSZ
#define ABUF_SZ (640 * AST * 2)           // 71680
#define SMT     (OFF_A + 2 * ABUF_SZ)     // 218112
// epilogue scratch aliased over A buffers (valid after final compute + bar)
#define OFF_SSQ OFF_A
#define OFF_SS2 (OFF_A + 256)
#define OFF_VSM (OFF_A + 272)

#define LDSM4(r0, r1, r2, r3, ad) \
    asm volatile("ldmatrix.sync.aligned.m8n8.x4.shared.b16 {%0,%1,%2,%3},[%4];" \
                 : "=r"(r0), "=r"(r1), "=r"(r2), "=r"(r3) : "r"(ad))

__global__ void __launch_bounds__(640, 1) k_gemm() {
    extern __shared__ char sm[];
    const int t = threadIdx.x, w = t >> 5, lane = t & 31;
    const int bid = blockIdx.x;
    const uint32_t sb = smem_u32(sm);

    // --- A chunk via cp.async: 640 rows x 96 B, 6 x 16B per thread ---
    auto issueA = [&](int c, int buf) {
        const int kc = KC * c;
#pragma unroll
        for (int i = 0; i < 6; i++) {
            int g = t + 640 * i;
            int row = g / 6, part = g % 6;
            const __half* src = g_W + (size_t)row * KE2 + kc + part * 8;
            uint32_t dst = sb + OFF_A + buf * ABUF_SZ + row * (AST * 2) + part * 16;
            asm volatile("cp.async.cg.shared.global [%0], [%1], 16;"
                         :: "r"(dst), "l"(src));
        }
        asm volatile("cp.async.commit_group;");
    };
    issueA(0, 0);

    // --- stage B (64 rows x 576 halves) ---
    const __half* Xb = g_X + (size_t)bid * TNB * KE2;
    for (int g = t; g < 64 * 72; g += 640) {
        int row = g / 72, part = g % 72;
        uint4 v = *reinterpret_cast<const uint4*>(Xb + (size_t)row * KE2 + part * 8);
        *reinterpret_cast<uint4*>(sm + OFF_B + row * (BST * 2) + part * 16) = v;
    }

    float acc[2][8][4];
#pragma unroll
    for (int mt = 0; mt < 2; mt++)
#pragma unroll
        for (int nt = 0; nt < 8; nt++)
#pragma unroll
            for (int c = 0; c < 4; c++) acc[mt][nt][c] = 0.f;

    // ldmatrix per-lane base addresses
    const int lm = lane >> 3;
    const uint32_t aAddr = sb + OFF_A +
        ((w * 32 + (lm & 1) * 8 + (lane & 7)) * AST + (lm >> 1) * 8) * 2;
    const uint32_t bAddr = sb + OFF_B +
        (((lm >> 1) * 8 + (lane & 7)) * BST + (lm & 1) * 8) * 2;

    for (int c = 0; c < NCH; c++) {
        const int buf = c & 1;
        asm volatile("cp.async.wait_group 0;");
        __syncthreads();                        // chunk c visible; c-1 compute done
        if (c + 1 < NCH) issueA(c + 1, buf ^ 1);

        const uint32_t aBuf = aAddr + buf * ABUF_SZ;
#pragma unroll
        for (int ks = 0; ks < 3; ks++) {
            uint32_t a0[4], a1[4];
            uint32_t aBase = aBuf + ks * 32;
            LDSM4(a0[0], a0[1], a0[2], a0[3], aBase);
            LDSM4(a1[0], a1[1], a1[2], a1[3], aBase + 16 * AST * 2);
#pragma unroll
            for (int ntp = 0; ntp < 4; ntp++) {
                uint32_t b[4];
                LDSM4(b[0], b[1], b[2], b[3],
                      bAddr + ntp * (16 * BST * 2) + c * (KC * 2) + ks * 32);
#pragma unroll
                for (int sub = 0; sub < 2; sub++) {
                    int nt = 2 * ntp + sub;
                    asm volatile(
                        "mma.sync.aligned.m16n8k16.row.col.f32.f16.f16.f32 "
                        "{%0,%1,%2,%3},{%4,%5,%6,%7},{%8,%9},{%0,%1,%2,%3};"
                        : "+f"(acc[0][nt][0]), "+f"(acc[0][nt][1]),
                          "+f"(acc[0][nt][2]), "+f"(acc[0][nt][3])
                        : "r"(a0[0]), "r"(a0[1]), "r"(a0[2]), "r"(a0[3]),
                          "r"(b[2 * sub]), "r"(b[2 * sub + 1]));
                    asm volatile(
                        "mma.sync.aligned.m16n8k16.row.col.f32.f16.f16.f32 "
                        "{%0,%1,%2,%3},{%4,%5,%6,%7},{%8,%9},{%0,%1,%2,%3};"
                        : "+f"(acc[1][nt][0]), "+f"(acc[1][nt][1]),
                          "+f"(acc[1][nt][2]), "+f"(acc[1][nt][3])
                        : "r"(a1[0]), "r"(a1[1]), "r"(a1[2]), "r"(a1[3]),
                          "r"(b[2 * sub]), "r"(b[2 * sub + 1]));
                }
            }
        }
    }
    __syncthreads();   // all compute done; A buffers now reusable as scratch

    float* ssq = reinterpret_cast<float*>(sm + OFF_SSQ);
    float* ss2 = reinterpret_cast<float*>(sm + OFF_SS2);
    float* vsm = reinterpret_cast<float*>(sm + OFF_VSM);
    if (t < 64) ssq[t] = 0.f;
    if (t >= 64 && t < 68) ss2[t - 64] = 0.f;
    __syncthreads();

    // ---- epilogue: per-position channel L2-norm ----
    {
        float cs[16];
#pragma unroll
        for (int nt = 0; nt < 8; nt++)
#pragma unroll
            for (int par = 0; par < 2; par++) {
                float s = 0.f;
#pragma unroll
                for (int mt = 0; mt < 2; mt++) {
                    float x0 = acc[mt][nt][par], x1 = acc[mt][nt][2 + par];
                    s = fmaf(x0, x0, s);
                    s = fmaf(x1, x1, s);
                }
                cs[nt * 2 + par] = s;
            }
#pragma unroll
        for (int i = 0; i < 16; i++) {
            cs[i] += __shfl_xor_sync(0xffffffffu, cs[i], 4);
            cs[i] += __shfl_xor_sync(0xffffffffu, cs[i], 8);
            cs[i] += __shfl_xor_sync(0xffffffffu, cs[i], 16);
        }
        if (lane < 4) {
#pragma unroll
            for (int nt = 0; nt < 8; nt++)
#pragma unroll
                for (int par = 0; par < 2; par++)
                    atomicAdd(&ssq[nt * 8 + lane * 2 + par], cs[nt * 2 + par]);
        }
    }
    __syncthreads();
    if (t < 64) ssq[t] = 1.f / fmaxf(sqrtf(ssq[t]), 1e-12f);
    __syncthreads();

    // ---- pool over positions + final channel L2-norm ----
    float sq[4] = {0.f, 0.f, 0.f, 0.f};
#pragma unroll
    for (int mt = 0; mt < 2; mt++)
#pragma unroll
        for (int h = 0; h < 2; h++)
#pragma unroll
            for (int j = 0; j < 4; j++) {
                float s = 0.f;
#pragma unroll
                for (int ntl = 0; ntl < 2; ntl++) {
                    int nt = 2 * j + ntl;
#pragma unroll
                    for (int par = 0; par < 2; par++) {
                        int col = nt * 8 + (lane & 3) * 2 + par;
                        s = fmaf(acc[mt][nt][h * 2 + par], ssq[col], s);
                    }
                }
                s += __shfl_xor_sync(0xffffffffu, s, 1);
                s += __shfl_xor_sync(0xffffffffu, s, 2);
                if ((lane & 3) == 0) {
                    int row = w * 32 + mt * 16 + h * 8 + (lane >> 2);
                    float v = s * 0.0625f;
                    vsm[row * 4 + j] = v;
                    sq[j] = fmaf(v, v, sq[j]);
                }
            }
#pragma unroll
    for (int j = 0; j < 4; j++) {
        sq[j] += __shfl_xor_sync(0xffffffffu, sq[j], 4);
        sq[j] += __shfl_xor_sync(0xffffffffu, sq[j], 8);
        sq[j] += __shfl_xor_sync(0xffffffffu, sq[j], 16);
    }
    if (lane == 0)
#pragma unroll
        for (int j = 0; j < 4; j++) atomicAdd(&ss2[j], sq[j]);
    __syncthreads();
    if (t < 4) ss2[t] = 1.f / fmaxf(sqrtf(ss2[t]), 1e-12f);
    __syncthreads();

    for (int g = t; g < 2560; g += 640) {
        int ch = g >> 2, j = g & 3;
        g_u[(size_t)(4 * bid + j) * CO + ch] = vsm[ch * 4 + j] * ss2[j];
    }
}

// ---------------------------------------------------------------------------
// Sim + greedy pruning. 600 blocks, 192 threads. Each dot split over 2
// threads with float4 accumulators (8 indep FMA chains, depth 80).
// ---------------------------------------------------------------------------
#define QSTRIDE 644

__global__ void __launch_bounds__(192) k_sim(float* __restrict__ out) {
    __shared__ float qsm[9 * QSTRIDE];
    __shared__ float ssm[9 * QSTRIDE];
    __shared__ float psum[162];
    __shared__ float simm[81];

    const int b = blockIdx.x / NQ_;
    const int n = blockIdx.x % NQ_;
    const int t = threadIdx.x;

    const float* qb = g_u + ((size_t)(b * 80 + WAY_ + n) * P_) * CO;
    for (int i = t; i < 9 * 160; i += 192) {
        int r = i / 160, c4 = (i % 160) * 4;
        *reinterpret_cast<float4*>(&qsm[r * QSTRIDE + c4]) =
            *reinterpret_cast<const float4*>(qb + (size_t)r * CO + c4);
    }

    for (int m = 0; m < WAY_; m++) {
        const float* sb2 = g_u + ((size_t)(b * 80 + m) * P_) * CO;
        __syncthreads();
        for (int i = t; i < 9 * 160; i += 192) {
            int r = i / 160, c4 = (i % 160) * 4;
            *reinterpret_cast<float4*>(&ssm[r * QSTRIDE + c4]) =
                *reinterpret_cast<const float4*>(sb2 + (size_t)r * CO + c4);
        }
        __syncthreads();

        if (t < 162) {
            const int pair = t >> 1;
            const int half = t & 1;
            const int h = pair / 9, wq = pair % 9;
            const float* sr = &ssm[h * QSTRIDE + half * 320];
            const float* qr = &qsm[wq * QSTRIDE + half * 320];
            float4 d0 = make_float4(0.f, 0.f, 0.f, 0.f);
            float4 d1 = make_float4(0.f, 0.f, 0.f, 0.f);
#pragma unroll 4
            for (int c = 0; c < 320; c += 8) {
                float4 a0 = *reinterpret_cast<const float4*>(sr + c);
                float4 q0 = *reinterpret_cast<const float4*>(qr + c);
                float4 a1 = *reinterpret_cast<const float4*>(sr + c + 4);
                float4 q1 = *reinterpret_cast<const float4*>(qr + c + 4);
                d0.x = fmaf(a0.x, q0.x, d0.x);
                d0.y = fmaf(a0.y, q0.y, d0.y);
                d0.z = fmaf(a0.z, q0.z, d0.z);
                d0.w = fmaf(a0.w, q0.w, d0.w);
                d1.x = fmaf(a1.x, q1.x, d1.x);
                d1.y = fmaf(a1.y, q1.y, d1.y);
                d1.z = fmaf(a1.z, q1.z, d1.z);
                d1.w = fmaf(a1.w, q1.w, d1.w);
            }
            psum[t] = (d0.x + d0.y) + (d0.z + d0.w)
                    + (d1.x + d1.y) + (d1.z + d1.w);
        }
        __syncthreads();
        if (t < 81) simm[t] = psum[2 * t] + psum[2 * t + 1];
        __syncthreads();

        if (t < 32) {
            float v0 = simm[t];
            float v1 = simm[t + 32];
            float v2 = (t + 64 < 81) ? simm[t + 64] : -1e30f;
            unsigned rmask = 0x1FFu, cmask = 0x1FFu;
            float totalv = 0.f, beta = 1.f;
            for (int it = 0; it < 9; it++) {
                float bv = -1e30f;
                int bidx = 999;
                int j = t;
                if (((rmask >> (j / 9)) & 1) && ((cmask >> (j % 9)) & 1)) {
                    bv = v0; bidx = j;
                }
                j = t + 32;
                if (((rmask >> (j / 9)) & 1) && ((cmask >> (j % 9)) & 1)) {
                    if (v1 > bv || (v1 == bv && j < bidx)) { bv = v1; bidx = j; }
                }
                j = t + 64;
                if (j < 81 && ((rmask >> (j / 9)) & 1) && ((cmask >> (j % 9)) & 1)) {
                    if (v2 > bv || (v2 == bv && j < bidx)) { bv = v2; bidx = j; }
                }
#pragma unroll
                for (int off = 16; off; off >>= 1) {
                    float ov = __shfl_xor_sync(0xffffffffu, bv, off);
                    int   oi = __shfl_xor_sync(0xffffffffu, bidx, off);
                    if (ov > bv || (ov == bv && oi < bidx)) { bv = ov; bidx = oi; }
                }
                totalv = fmaf(fmaxf(bv, 0.f), beta, totalv);
                beta *= 0.5f;
                rmask &= ~(1u << (bidx / 9));
                cmask &= ~(1u << (bidx % 9));
            }
            if (t == 0) out[((size_t)b * NQ_ + n) * WAY_ + m] = totalv;
        }
    }
}

// ---------------------------------------------------------------------------
extern "C" void kernel_launch(void* const* d_in, const int* in_sizes, int n_in,
                              void* d_out, int out_size) {
    const float* data   = (const float*)d_in[0];
    const float* conv_w = (const float*)d_in[1];
    (void)in_sizes; (void)n_in; (void)out_size;

    static bool attr_set = false;
    if (!attr_set) {
        cudaFuncSetAttribute(k_gemm, cudaFuncAttributeMaxDynamicSharedMemorySize, SMT);
        attr_set = true;
    }

    k_prepw<<<(CO * KD + 255) / 256, 256>>>(conv_w);
    k_prepx<<<NS, 128>>>(data);
    k_gemm<<<NTOT / TNB, 640, SMT>>>();
    k_sim<<<B_ * NQ_, 192>>>((float*)d_out);
}

// round 8
// speedup vs baseline: 1.2538x; 1.2538x over previous
#include <cuda_runtime.h>
#include <cuda_fp16.h>
#include <cstdint>
#include <math.h>

// ---------------- problem constants ----------------
#define NS   5760
#define CO   640
#define KD   192
#define NPOS 16
#define B_   8
#define WAY_ 5
#define NQ_  75
#define P_   9
#define NTOT (NS * NPOS)     // 92160
#define KE2  576             // 3 * 192 fp16-split K
#define TNB  64              // N per block = 4 images
#define KC   32              // K halves per chunk
#define NCH  18              // 576 / 32

// ---------------- device scratch ----------------
__device__ __align__(128) __half g_X[(size_t)NTOT * KE2];  // 106 MB
__device__ __align__(128) __half g_W[(size_t)CO * KE2];    // 737 KB
__device__ float g_u[(size_t)NS * CO];

__device__ __forceinline__ uint32_t smem_u32(const void* p) {
    uint32_t a;
    asm("{ .reg .u64 t; cvta.to.shared.u64 t, %1; cvt.u32.u64 %0, t; }"
        : "=r"(a) : "l"(p));
    return a;
}

// ---------------------------------------------------------------------------
// Prep W: fp16 split, K-concat [w0 | w0 | w1]
// ---------------------------------------------------------------------------
__global__ void k_prepw(const float* __restrict__ w) {
    int i = blockIdx.x * 256 + threadIdx.x;
    if (i >= CO * KD) return;
    int ch = i / KD, k = i % KD;
    float v = w[i];
    __half h0 = __float2half_rn(v);
    __half h1 = __float2half_rn(v - __half2float(h0));
    size_t b = (size_t)ch * KE2;
    g_W[b + k]       = h0;
    g_W[b + 192 + k] = h0;
    g_W[b + 384 + k] = h1;
}

// ---------------------------------------------------------------------------
// Prep X: im2col + fp16 split, K-concat [x0 | x1 | x0]. One block per image.
// ---------------------------------------------------------------------------
__global__ void __launch_bounds__(128) k_prepx(const float* __restrict__ data) {
    __shared__ __align__(16) __half xsm[NPOS * KE2];   // 18 KB
    const int s = blockIdx.x, t = threadIdx.x;
    const float* img = data + (size_t)s * 3072;
    for (int i = t; i < 3072; i += 128) {
        float v = img[i];
        int ci = i >> 10, row = (i >> 5) & 31, col = i & 31;
        int k   = ci * 64 + (row & 7) * 8 + (col & 7);
        int pos = (row >> 3) * 4 + (col >> 3);
        __half h0 = __float2half_rn(v);
        __half h1 = __float2half_rn(v - __half2float(h0));
        int r = pos * KE2;
        xsm[r + k]       = h0;
        xsm[r + 192 + k] = h1;
        xsm[r + 384 + k] = h0;
    }
    __syncthreads();
    uint4* dst = reinterpret_cast<uint4*>(g_X + (size_t)s * NPOS * KE2);
    const uint4* src = reinterpret_cast<const uint4*>(xsm);
    for (int g = t; g < NPOS * KE2 / 8; g += 128) dst[g] = src[g];
}

// ---------------------------------------------------------------------------
// Fused GEMM + norms. Triple-buffered A, ONE barrier per chunk. (R6, 415µs)
// ---------------------------------------------------------------------------
#define BST     584                       // B row stride (halves): 1168 B
#define AST     40                        // A row stride (halves): 80 B
#define OFF_B   0
#define BSZ     (64 * BST * 2)            // 74752
#define OFF_A   BSZ
#define ABUF_SZ (640 * AST * 2)           // 51200
#define SMT     (OFF_A + 3 * ABUF_SZ)     // 228352
#define OFF_SSQ OFF_A
#define OFF_SS2 (OFF_A + 256)
#define OFF_VSM (OFF_A + 272)

#define LDSM4(r0, r1, r2, r3, ad) \
    asm volatile("ldmatrix.sync.aligned.m8n8.x4.shared.b16 {%0,%1,%2,%3},[%4];" \
                 : "=r"(r0), "=r"(r1), "=r"(r2), "=r"(r3) : "r"(ad))

__global__ void __launch_bounds__(640, 1) k_gemm() {
    extern __shared__ char sm[];
    const int t = threadIdx.x, w = t >> 5, lane = t & 31;
    const int bid = blockIdx.x;
    const uint32_t sb = smem_u32(sm);

    auto issueA = [&](int c, int buf) {
        const int kc = KC * c;
#pragma unroll
        for (int i = 0; i < 4; i++) {
            int g = t + 640 * i;
            int row = g >> 2, part = g & 3;
            const __half* src = g_W + (size_t)row * KE2 + kc + part * 8;
            uint32_t dst = sb + OFF_A + buf * ABUF_SZ + row * (AST * 2) + part * 16;
            asm volatile("cp.async.cg.shared.global [%0], [%1], 16;"
                         :: "r"(dst), "l"(src));
        }
        asm volatile("cp.async.commit_group;");
    };
    issueA(0, 0);
    issueA(1, 1);

    const __half* Xb = g_X + (size_t)bid * TNB * KE2;
    for (int g = t; g < 64 * 72; g += 640) {
        int row = g / 72, part = g % 72;
        uint4 v = *reinterpret_cast<const uint4*>(Xb + (size_t)row * KE2 + part * 8);
        *reinterpret_cast<uint4*>(sm + OFF_B + row * (BST * 2) + part * 16) = v;
    }

    float acc[2][8][4];
#pragma unroll
    for (int mt = 0; mt < 2; mt++)
#pragma unroll
        for (int nt = 0; nt < 8; nt++)
#pragma unroll
            for (int c = 0; c < 4; c++) acc[mt][nt][c] = 0.f;

    const int lm = lane >> 3;
    const uint32_t aAddr = sb + OFF_A +
        ((w * 32 + (lm & 1) * 8 + (lane & 7)) * AST + (lm >> 1) * 8) * 2;
    const uint32_t bAddr = sb + OFF_B +
        (((lm >> 1) * 8 + (lane & 7)) * BST + (lm & 1) * 8) * 2;

    for (int c = 0; c < NCH; c++) {
        if (c + 1 < NCH) asm volatile("cp.async.wait_group 1;");
        else             asm volatile("cp.async.wait_group 0;");
        __syncthreads();
        if (c + 2 < NCH) issueA(c + 2, (c + 2) % 3);

        const uint32_t aBuf = aAddr + (c % 3) * ABUF_SZ;
#pragma unroll
        for (int ks = 0; ks < 2; ks++) {
            uint32_t a0[4], a1[4];
            uint32_t aBase = aBuf + ks * 32;
            LDSM4(a0[0], a0[1], a0[2], a0[3], aBase);
            LDSM4(a1[0], a1[1], a1[2], a1[3], aBase + 16 * AST * 2);
#pragma unroll
            for (int ntp = 0; ntp < 4; ntp++) {
                uint32_t b[4];
                LDSM4(b[0], b[1], b[2], b[3],
                      bAddr + ntp * (16 * BST * 2) + c * (KC * 2) + ks * 32);
#pragma unroll
                for (int sub = 0; sub < 2; sub++) {
                    int nt = 2 * ntp + sub;
                    asm volatile(
                        "mma.sync.aligned.m16n8k16.row.col.f32.f16.f16.f32 "
                        "{%0,%1,%2,%3},{%4,%5,%6,%7},{%8,%9},{%0,%1,%2,%3};"
                        : "+f"(acc[0][nt][0]), "+f"(acc[0][nt][1]),
                          "+f"(acc[0][nt][2]), "+f"(acc[0][nt][3])
                        : "r"(a0[0]), "r"(a0[1]), "r"(a0[2]), "r"(a0[3]),
                          "r"(b[2 * sub]), "r"(b[2 * sub + 1]));
                    asm volatile(
                        "mma.sync.aligned.m16n8k16.row.col.f32.f16.f16.f32 "
                        "{%0,%1,%2,%3},{%4,%5,%6,%7},{%8,%9},{%0,%1,%2,%3};"
                        : "+f"(acc[1][nt][0]), "+f"(acc[1][nt][1]),
                          "+f"(acc[1][nt][2]), "+f"(acc[1][nt][3])
                        : "r"(a1[0]), "r"(a1[1]), "r"(a1[2]), "r"(a1[3]),
                          "r"(b[2 * sub]), "r"(b[2 * sub + 1]));
                }
            }
        }
    }
    __syncthreads();

    float* ssq = reinterpret_cast<float*>(sm + OFF_SSQ);
    float* ss2 = reinterpret_cast<float*>(sm + OFF_SS2);
    float* vsm = reinterpret_cast<float*>(sm + OFF_VSM);
    if (t < 64) ssq[t] = 0.f;
    if (t >= 64 && t < 68) ss2[t - 64] = 0.f;
    __syncthreads();

    {
        float cs[16];
#pragma unroll
        for (int nt = 0; nt < 8; nt++)
#pragma unroll
            for (int par = 0; par < 2; par++) {
                float s = 0.f;
#pragma unroll
                for (int mt = 0; mt < 2; mt++) {
                    float x0 = acc[mt][nt][par], x1 = acc[mt][nt][2 + par];
                    s = fmaf(x0, x0, s);
                    s = fmaf(x1, x1, s);
                }
                cs[nt * 2 + par] = s;
            }
#pragma unroll
        for (int i = 0; i < 16; i++) {
            cs[i] += __shfl_xor_sync(0xffffffffu, cs[i], 4);
            cs[i] += __shfl_xor_sync(0xffffffffu, cs[i], 8);
            cs[i] += __shfl_xor_sync(0xffffffffu, cs[i], 16);
        }
        if (lane < 4) {
#pragma unroll
            for (int nt = 0; nt < 8; nt++)
#pragma unroll
                for (int par = 0; par < 2; par++)
                    atomicAdd(&ssq[nt * 8 + lane * 2 + par], cs[nt * 2 + par]);
        }
    }
    __syncthreads();
    if (t < 64) ssq[t] = 1.f / fmaxf(sqrtf(ssq[t]), 1e-12f);
    __syncthreads();

    float sq[4] = {0.f, 0.f, 0.f, 0.f};
#pragma unroll
    for (int mt = 0; mt < 2; mt++)
#pragma unroll
        for (int h = 0; h < 2; h++)
#pragma unroll
            for (int j = 0; j < 4; j++) {
                float s = 0.f;
#pragma unroll
                for (int ntl = 0; ntl < 2; ntl++) {
                    int nt = 2 * j + ntl;
#pragma unroll
                    for (int par = 0; par < 2; par++) {
                        int col = nt * 8 + (lane & 3) * 2 + par;
                        s = fmaf(acc[mt][nt][h * 2 + par], ssq[col], s);
                    }
                }
                s += __shfl_xor_sync(0xffffffffu, s, 1);
                s += __shfl_xor_sync(0xffffffffu, s, 2);
                if ((lane & 3) == 0) {
                    int row = w * 32 + mt * 16 + h * 8 + (lane >> 2);
                    float v = s * 0.0625f;
                    vsm[row * 4 + j] = v;
                    sq[j] = fmaf(v, v, sq[j]);
                }
            }
#pragma unroll
    for (int j = 0; j < 4; j++) {
        sq[j] += __shfl_xor_sync(0xffffffffu, sq[j], 4);
        sq[j] += __shfl_xor_sync(0xffffffffu, sq[j], 8);
        sq[j] += __shfl_xor_sync(0xffffffffu, sq[j], 16);
    }
    if (lane == 0)
#pragma unroll
        for (int j = 0; j < 4; j++) atomicAdd(&ss2[j], sq[j]);
    __syncthreads();
    if (t < 4) ss2[t] = 1.f / fmaxf(sqrtf(ss2[t]), 1e-12f);
    __syncthreads();

    for (int g = t; g < 2560; g += 640) {
        int ch = g >> 2, j = g & 3;
        g_u[(size_t)(4 * bid + j) * CO + ch] = vsm[ch * 4 + j] * ss2[j];
    }
}

// ---------------------------------------------------------------------------
// Sim + greedy. Register-tiled: thread (tile tt in [0,9), slice ss in [0,16))
// computes a 3x3 output tile over 40 k's -> 3x fewer LDS bytes per FLOP.
// Deterministic two-stage reduction via psum[144][9].
// ---------------------------------------------------------------------------
#define QSTRIDE 644

__global__ void __launch_bounds__(160) k_sim(float* __restrict__ out) {
    __shared__ float qsm[9 * QSTRIDE];
    __shared__ float ssm[9 * QSTRIDE];
    __shared__ float psum[144][9];
    __shared__ float simm[81];

    const int b = blockIdx.x / NQ_;
    const int n = blockIdx.x % NQ_;
    const int t = threadIdx.x;

    const float* qb = g_u + ((size_t)(b * 80 + WAY_ + n) * P_) * CO;
    for (int i = t; i < 9 * 160; i += 160) {
        int r = i / 160, c4 = (i % 160) * 4;
        *reinterpret_cast<float4*>(&qsm[r * QSTRIDE + c4]) =
            *reinterpret_cast<const float4*>(qb + (size_t)r * CO + c4);
    }

    const int tt = t >> 4;          // tile 0..9 (t<144)
    const int ss = t & 15;          // k-slice 0..15
    const int h0 = (tt / 3) * 3;
    const int w0 = (tt % 3) * 3;
    const int k0 = ss * 40;

    for (int m = 0; m < WAY_; m++) {
        const float* sbp = g_u + ((size_t)(b * 80 + m) * P_) * CO;
        __syncthreads();
        for (int i = t; i < 9 * 160; i += 160) {
            int r = i / 160, c4 = (i % 160) * 4;
            *reinterpret_cast<float4*>(&ssm[r * QSTRIDE + c4]) =
                *reinterpret_cast<const float4*>(sbp + (size_t)r * CO + c4);
        }
        __syncthreads();

        if (t < 144) {
            float a00 = 0.f, a01 = 0.f, a02 = 0.f;
            float a10 = 0.f, a11 = 0.f, a12 = 0.f;
            float a20 = 0.f, a21 = 0.f, a22 = 0.f;
            const float* s0 = &ssm[(h0 + 0) * QSTRIDE + k0];
            const float* s1 = &ssm[(h0 + 1) * QSTRIDE + k0];
            const float* s2 = &ssm[(h0 + 2) * QSTRIDE + k0];
            const float* q0 = &qsm[(w0 + 0) * QSTRIDE + k0];
            const float* q1 = &qsm[(w0 + 1) * QSTRIDE + k0];
            const float* q2 = &qsm[(w0 + 2) * QSTRIDE + k0];
#pragma unroll 2
            for (int k = 0; k < 40; k += 4) {
                float4 sv0 = *reinterpret_cast<const float4*>(s0 + k);
                float4 sv1 = *reinterpret_cast<const float4*>(s1 + k);
                float4 sv2 = *reinterpret_cast<const float4*>(s2 + k);
                float4 qv0 = *reinterpret_cast<const float4*>(q0 + k);
                float4 qv1 = *reinterpret_cast<const float4*>(q1 + k);
                float4 qv2 = *reinterpret_cast<const float4*>(q2 + k);
                a00 = fmaf(sv0.x, qv0.x, a00); a00 = fmaf(sv0.y, qv0.y, a00);
                a00 = fmaf(sv0.z, qv0.z, a00); a00 = fmaf(sv0.w, qv0.w, a00);
                a01 = fmaf(sv0.x, qv1.x, a01); a01 = fmaf(sv0.y, qv1.y, a01);
                a01 = fmaf(sv0.z, qv1.z, a01); a01 = fmaf(sv0.w, qv1.w, a01);
                a02 = fmaf(sv0.x, qv2.x, a02); a02 = fmaf(sv0.y, qv2.y, a02);
                a02 = fmaf(sv0.z, qv2.z, a02); a02 = fmaf(sv0.w, qv2.w, a02);
                a10 = fmaf(sv1.x, qv0.x, a10); a10 = fmaf(sv1.y, qv0.y, a10);
                a10 = fmaf(sv1.z, qv0.z, a10); a10 = fmaf(sv1.w, qv0.w, a10);
                a11 = fmaf(sv1.x, qv1.x, a11); a11 = fmaf(sv1.y, qv1.y, a11);
                a11 = fmaf(sv1.z, qv1.z, a11); a11 = fmaf(sv1.w, qv1.w, a11);
                a12 = fmaf(sv1.x, qv2.x, a12); a12 = fmaf(sv1.y, qv2.y, a12);
                a12 = fmaf(sv1.z, qv2.z, a12); a12 = fmaf(sv1.w, qv2.w, a12);
                a20 = fmaf(sv2.x, qv0.x, a20); a20 = fmaf(sv2.y, qv0.y, a20);
                a20 = fmaf(sv2.z, qv0.z, a20); a20 = fmaf(sv2.w, qv0.w, a20);
                a21 = fmaf(sv2.x, qv1.x, a21); a21 = fmaf(sv2.y, qv1.y, a21);
                a21 = fmaf(sv2.z, qv1.z, a21); a21 = fmaf(sv2.w, qv1.w, a21);
                a22 = fmaf(sv2.x, qv2.x, a22); a22 = fmaf(sv2.y, qv2.y, a22);
                a22 = fmaf(sv2.z, qv2.z, a22); a22 = fmaf(sv2.w, qv2.w, a22);
            }
            float* pr = psum[t];
            pr[0] = a00; pr[1] = a01; pr[2] = a02;
            pr[3] = a10; pr[4] = a11; pr[5] = a12;
            pr[6] = a20; pr[7] = a21; pr[8] = a22;
        }
        __syncthreads();
        if (t < 81) {
            int h = t / 9, wq = t % 9;
            int tile = (h / 3) * 3 + wq / 3;
            int e = (h % 3) * 3 + (wq % 3);
            float s = 0.f;
#pragma unroll
            for (int k = 0; k < 16; k++) s += psum[tile * 16 + k][e];
            simm[t] = s;
        }
        __syncthreads();

        if (t < 32) {
            float v0 = simm[t];
            float v1 = simm[t + 32];
            float v2 = (t + 64 < 81) ? simm[t + 64] : -1e30f;
            unsigned rmask = 0x1FFu, cmask = 0x1FFu;
            float totalv = 0.f, beta = 1.f;
            for (int it = 0; it < 9; it++) {
                float bv = -1e30f;
                int bidx = 999;
                int j = t;
                if (((rmask >> (j / 9)) & 1) && ((cmask >> (j % 9)) & 1)) {
                    bv = v0; bidx = j;
                }
                j = t + 32;
                if (((rmask >> (j / 9)) & 1) && ((cmask >> (j % 9)) & 1)) {
                    if (v1 > bv || (v1 == bv && j < bidx)) { bv = v1; bidx = j; }
                }
                j = t + 64;
                if (j < 81 && ((rmask >> (j / 9)) & 1) && ((cmask >> (j % 9)) & 1)) {
                    if (v2 > bv || (v2 == bv && j < bidx)) { bv = v2; bidx = j; }
                }
#pragma unroll
                for (int off = 16; off; off >>= 1) {
                    float ov = __shfl_xor_sync(0xffffffffu, bv, off);
                    int   oi = __shfl_xor_sync(0xffffffffu, bidx, off);
                    if (ov > bv || (ov == bv && oi < bidx)) { bv = ov; bidx = oi; }
                }
                totalv = fmaf(fmaxf(bv, 0.f), beta, totalv);
                beta *= 0.5f;
                rmask &= ~(1u << (bidx / 9));
                cmask &= ~(1u << (bidx % 9));
            }
            if (t == 0) out[((size_t)b * NQ_ + n) * WAY_ + m] = totalv;
        }
    }
}

// ---------------------------------------------------------------------------
extern "C" void kernel_launch(void* const* d_in, const int* in_sizes, int n_in,
                              void* d_out, int out_size) {
    const float* data   = (const float*)d_in[0];
    const float* conv_w = (const float*)d_in[1];
    (void)in_sizes; (void)n_in; (void)out_size;

    static bool attr_set = false;
    if (!attr_set) {
        cudaFuncSetAttribute(k_gemm, cudaFuncAttributeMaxDynamicSharedMemorySize, SMT);
        attr_set = true;
    }

    k_prepw<<<(CO * KD + 255) / 256, 256>>>(conv_w);
    k_prepx<<<NS, 128>>>(data);
    k_gemm<<<NTOT / TNB, 640, SMT>>>();
    k_sim<<<B_ * NQ_, 160>>>((float*)d_out);
}

// round 9
// speedup vs baseline: 1.3748x; 1.0966x over previous
#include <cuda_runtime.h>
#include <cuda_fp16.h>
#include <cstdint>
#include <math.h>

// ---------------- problem constants ----------------
#define NS   5760
#define CO   640
#define KD   192
#define NPOS 16
#define B_   8
#define WAY_ 5
#define NQ_  75
#define P_   9
#define NTOT (NS * NPOS)     // 92160
#define KE2  576             // 3 * 192 fp16-split K
#define TNB  64              // N per block = 4 images
#define KC   32              // K halves per chunk
#define NCH  18              // 576 / 32

// ---------------- device scratch ----------------
__device__ __align__(128) __half g_X[(size_t)NTOT * KE2];  // 106 MB
__device__ __align__(128) __half g_W[(size_t)CO * KE2];    // 737 KB
__device__ float g_u[(size_t)NS * CO];

__device__ __forceinline__ uint32_t smem_u32(const void* p) {
    uint32_t a;
    asm("{ .reg .u64 t; cvta.to.shared.u64 t, %1; cvt.u32.u64 %0, t; }"
        : "=r"(a) : "l"(p));
    return a;
}

// ---------------------------------------------------------------------------
// Prep W: fp16 split, K-concat [w0 | w0 | w1]
// ---------------------------------------------------------------------------
__global__ void k_prepw(const float* __restrict__ w) {
    int i = blockIdx.x * 256 + threadIdx.x;
    if (i >= CO * KD) return;
    int ch = i / KD, k = i % KD;
    float v = w[i];
    __half h0 = __float2half_rn(v);
    __half h1 = __float2half_rn(v - __half2float(h0));
    size_t b = (size_t)ch * KE2;
    g_W[b + k]       = h0;
    g_W[b + 192 + k] = h0;
    g_W[b + 384 + k] = h1;
}

// ---------------------------------------------------------------------------
// Prep X: im2col + fp16 split, K-concat [x0 | x1 | x0]. One block per image.
// ---------------------------------------------------------------------------
__global__ void __launch_bounds__(128) k_prepx(const float* __restrict__ data) {
    __shared__ __align__(16) __half xsm[NPOS * KE2];   // 18 KB
    const int s = blockIdx.x, t = threadIdx.x;
    const float* img = data + (size_t)s * 3072;
    for (int i = t; i < 3072; i += 128) {
        float v = img[i];
        int ci = i >> 10, row = (i >> 5) & 31, col = i & 31;
        int k   = ci * 64 + (row & 7) * 8 + (col & 7);
        int pos = (row >> 3) * 4 + (col >> 3);
        __half h0 = __float2half_rn(v);
        __half h1 = __float2half_rn(v - __half2float(h0));
        int r = pos * KE2;
        xsm[r + k]       = h0;
        xsm[r + 192 + k] = h1;
        xsm[r + 384 + k] = h0;
    }
    __syncthreads();
    uint4* dst = reinterpret_cast<uint4*>(g_X + (size_t)s * NPOS * KE2);
    const uint4* src = reinterpret_cast<const uint4*>(xsm);
    for (int g = t; g < NPOS * KE2 / 8; g += 128) dst[g] = src[g];
}

// ---------------------------------------------------------------------------
// Fused GEMM + norms. A staged PER-WARP (warp-private rows) with triple
// buffering; NO block-wide sync in the mainloop. B staged once.
// ---------------------------------------------------------------------------
#define BST      584                      // B row stride (halves): 1168 B
#define AST      40                       // A row stride (halves): 80 B
#define OFF_B    0
#define BSZ      (64 * BST * 2)           // 74752
#define OFF_A    BSZ
#define ABUF_SZ  (32 * AST * 2)           // 2560 per warp-buffer
#define AWARP_SZ (3 * ABUF_SZ)            // 7680 per warp
#define SMT      (OFF_A + 20 * AWARP_SZ)  // 228352
#define OFF_SSQ  OFF_A
#define OFF_SS2  (OFF_A + 256)
#define OFF_VSM  (OFF_A + 272)

#define LDSM4(r0, r1, r2, r3, ad) \
    asm volatile("ldmatrix.sync.aligned.m8n8.x4.shared.b16 {%0,%1,%2,%3},[%4];" \
                 : "=r"(r0), "=r"(r1), "=r"(r2), "=r"(r3) : "r"(ad))

__global__ void __launch_bounds__(640, 1) k_gemm() {
    extern __shared__ char sm[];
    const int t = threadIdx.x, w = t >> 5, lane = t & 31;
    const int bid = blockIdx.x;
    const uint32_t sb = smem_u32(sm);
    const uint32_t aWarpBase = sb + OFF_A + w * AWARP_SZ;

    // --- per-warp A chunk: 32 rows x 64 B, 4 x 16B per lane ---
    auto issueA = [&](int c, int buf) {
        const int kc = KC * c;
#pragma unroll
        for (int i = 0; i < 4; i++) {
            int g = lane + 32 * i;
            int row = g >> 2, part = g & 3;
            const __half* src = g_W + (size_t)(w * 32 + row) * KE2 + kc + part * 8;
            uint32_t dst = aWarpBase + buf * ABUF_SZ + row * (AST * 2) + part * 16;
            asm volatile("cp.async.cg.shared.global [%0], [%1], 16;"
                         :: "r"(dst), "l"(src));
        }
        asm volatile("cp.async.commit_group;");
    };
    issueA(0, 0);
    issueA(1, 1);

    // --- stage B once (64 rows x 576 halves) ---
    const __half* Xb = g_X + (size_t)bid * TNB * KE2;
    for (int g = t; g < 64 * 72; g += 640) {
        int row = g / 72, part = g % 72;
        uint4 v = *reinterpret_cast<const uint4*>(Xb + (size_t)row * KE2 + part * 8);
        *reinterpret_cast<uint4*>(sm + OFF_B + row * (BST * 2) + part * 16) = v;
    }
    __syncthreads();   // ONLY block-wide sync before epilogue

    float acc[2][8][4];
#pragma unroll
    for (int mt = 0; mt < 2; mt++)
#pragma unroll
        for (int nt = 0; nt < 8; nt++)
#pragma unroll
            for (int c = 0; c < 4; c++) acc[mt][nt][c] = 0.f;

    const int lm = lane >> 3;
    const uint32_t aAddr = aWarpBase +
        (((lm & 1) * 8 + (lane & 7)) * AST + (lm >> 1) * 8) * 2;
    const uint32_t bAddr = sb + OFF_B +
        (((lm >> 1) * 8 + (lane & 7)) * BST + (lm & 1) * 8) * 2;

    for (int c = 0; c < NCH; c++) {
        if (c + 1 < NCH) asm volatile("cp.async.wait_group 1;");
        else             asm volatile("cp.async.wait_group 0;");
        __syncwarp();                       // warp-local visibility only
        if (c + 2 < NCH) issueA(c + 2, (c + 2) % 3);

        const uint32_t aBuf = aAddr + (c % 3) * ABUF_SZ;
#pragma unroll
        for (int ks = 0; ks < 2; ks++) {
            uint32_t a0[4], a1[4];
            uint32_t aBase = aBuf + ks * 32;
            LDSM4(a0[0], a0[1], a0[2], a0[3], aBase);
            LDSM4(a1[0], a1[1], a1[2], a1[3], aBase + 16 * AST * 2);
#pragma unroll
            for (int ntp = 0; ntp < 4; ntp++) {
                uint32_t b[4];
                LDSM4(b[0], b[1], b[2], b[3],
                      bAddr + ntp * (16 * BST * 2) + c * (KC * 2) + ks * 32);
#pragma unroll
                for (int sub = 0; sub < 2; sub++) {
                    int nt = 2 * ntp + sub;
                    asm volatile(
                        "mma.sync.aligned.m16n8k16.row.col.f32.f16.f16.f32 "
                        "{%0,%1,%2,%3},{%4,%5,%6,%7},{%8,%9},{%0,%1,%2,%3};"
                        : "+f"(acc[0][nt][0]), "+f"(acc[0][nt][1]),
                          "+f"(acc[0][nt][2]), "+f"(acc[0][nt][3])
                        : "r"(a0[0]), "r"(a0[1]), "r"(a0[2]), "r"(a0[3]),
                          "r"(b[2 * sub]), "r"(b[2 * sub + 1]));
                    asm volatile(
                        "mma.sync.aligned.m16n8k16.row.col.f32.f16.f16.f32 "
                        "{%0,%1,%2,%3},{%4,%5,%6,%7},{%8,%9},{%0,%1,%2,%3};"
                        : "+f"(acc[1][nt][0]), "+f"(acc[1][nt][1]),
                          "+f"(acc[1][nt][2]), "+f"(acc[1][nt][3])
                        : "r"(a1[0]), "r"(a1[1]), "r"(a1[2]), "r"(a1[3]),
                          "r"(b[2 * sub]), "r"(b[2 * sub + 1]));
                }
            }
        }
    }
    __syncthreads();   // all warps done; A region reusable as scratch

    float* ssq = reinterpret_cast<float*>(sm + OFF_SSQ);
    float* ss2 = reinterpret_cast<float*>(sm + OFF_SS2);
    float* vsm = reinterpret_cast<float*>(sm + OFF_VSM);
    if (t < 64) ssq[t] = 0.f;
    if (t >= 64 && t < 68) ss2[t - 64] = 0.f;
    __syncthreads();

    // ---- epilogue: per-position channel L2-norm ----
    {
        float cs[16];
#pragma unroll
        for (int nt = 0; nt < 8; nt++)
#pragma unroll
            for (int par = 0; par < 2; par++) {
                float s = 0.f;
#pragma unroll
                for (int mt = 0; mt < 2; mt++) {
                    float x0 = acc[mt][nt][par], x1 = acc[mt][nt][2 + par];
                    s = fmaf(x0, x0, s);
                    s = fmaf(x1, x1, s);
                }
                cs[nt * 2 + par] = s;
            }
#pragma unroll
        for (int i = 0; i < 16; i++) {
            cs[i] += __shfl_xor_sync(0xffffffffu, cs[i], 4);
            cs[i] += __shfl_xor_sync(0xffffffffu, cs[i], 8);
            cs[i] += __shfl_xor_sync(0xffffffffu, cs[i], 16);
        }
        if (lane < 4) {
#pragma unroll
            for (int nt = 0; nt < 8; nt++)
#pragma unroll
                for (int par = 0; par < 2; par++)
                    atomicAdd(&ssq[nt * 8 + lane * 2 + par], cs[nt * 2 + par]);
        }
    }
    __syncthreads();
    if (t < 64) ssq[t] = 1.f / fmaxf(sqrtf(ssq[t]), 1e-12f);
    __syncthreads();

    // ---- pool over positions + final channel L2-norm ----
    float sq[4] = {0.f, 0.f, 0.f, 0.f};
#pragma unroll
    for (int mt = 0; mt < 2; mt++)
#pragma unroll
        for (int h = 0; h < 2; h++)
#pragma unroll
            for (int j = 0; j < 4; j++) {
                float s = 0.f;
#pragma unroll
                for (int ntl = 0; ntl < 2; ntl++) {
                    int nt = 2 * j + ntl;
#pragma unroll
                    for (int par = 0; par < 2; par++) {
                        int col = nt * 8 + (lane & 3) * 2 + par;
                        s = fmaf(acc[mt][nt][h * 2 + par], ssq[col], s);
                    }
                }
                s += __shfl_xor_sync(0xffffffffu, s, 1);
                s += __shfl_xor_sync(0xffffffffu, s, 2);
                if ((lane & 3) == 0) {
                    int row = w * 32 + mt * 16 + h * 8 + (lane >> 2);
                    float v = s * 0.0625f;
                    vsm[row * 4 + j] = v;
                    sq[j] = fmaf(v, v, sq[j]);
                }
            }
#pragma unroll
    for (int j = 0; j < 4; j++) {
        sq[j] += __shfl_xor_sync(0xffffffffu, sq[j], 4);
        sq[j] += __shfl_xor_sync(0xffffffffu, sq[j], 8);
        sq[j] += __shfl_xor_sync(0xffffffffu, sq[j], 16);
    }
    if (lane == 0)
#pragma unroll
        for (int j = 0; j < 4; j++) atomicAdd(&ss2[j], sq[j]);
    __syncthreads();
    if (t < 4) ss2[t] = 1.f / fmaxf(sqrtf(ss2[t]), 1e-12f);
    __syncthreads();

    for (int g = t; g < 2560; g += 640) {
        int ch = g >> 2, j = g & 3;
        g_u[(size_t)(4 * bid + j) * CO + ch] = vsm[ch * 4 + j] * ss2[j];
    }
}

// ---------------------------------------------------------------------------
// Sim + greedy. Register-tiled 3x3 (R8, 47 µs) — unchanged.
// ---------------------------------------------------------------------------
#define QSTRIDE 644

__global__ void __launch_bounds__(160) k_sim(float* __restrict__ out) {
    __shared__ float qsm[9 * QSTRIDE];
    __shared__ float ssm[9 * QSTRIDE];
    __shared__ float psum[144][9];
    __shared__ float simm[81];

    const int b = blockIdx.x / NQ_;
    const int n = blockIdx.x % NQ_;
    const int t = threadIdx.x;

    const float* qb = g_u + ((size_t)(b * 80 + WAY_ + n) * P_) * CO;
    for (int i = t; i < 9 * 160; i += 160) {
        int r = i / 160, c4 = (i % 160) * 4;
        *reinterpret_cast<float4*>(&qsm[r * QSTRIDE + c4]) =
            *reinterpret_cast<const float4*>(qb + (size_t)r * CO + c4);
    }

    const int tt = t >> 4;
    const int ss = t & 15;
    const int h0 = (tt / 3) * 3;
    const int w0 = (tt % 3) * 3;
    const int k0 = ss * 40;

    for (int m = 0; m < WAY_; m++) {
        const float* sbp = g_u + ((size_t)(b * 80 + m) * P_) * CO;
        __syncthreads();
        for (int i = t; i < 9 * 160; i += 160) {
            int r = i / 160, c4 = (i % 160) * 4;
            *reinterpret_cast<float4*>(&ssm[r * QSTRIDE + c4]) =
                *reinterpret_cast<const float4*>(sbp + (size_t)r * CO + c4);
        }
        __syncthreads();

        if (t < 144) {
            float a00 = 0.f, a01 = 0.f, a02 = 0.f;
            float a10 = 0.f, a11 = 0.f, a12 = 0.f;
            float a20 = 0.f, a21 = 0.f, a22 = 0.f;
            const float* s0 = &ssm[(h0 + 0) * QSTRIDE + k0];
            const float* s1 = &ssm[(h0 + 1) * QSTRIDE + k0];
            const float* s2 = &ssm[(h0 + 2) * QSTRIDE + k0];
            const float* q0 = &qsm[(w0 + 0) * QSTRIDE + k0];
            const float* q1 = &qsm[(w0 + 1) * QSTRIDE + k0];
            const float* q2 = &qsm[(w0 + 2) * QSTRIDE + k0];
#pragma unroll 2
            for (int k = 0; k < 40; k += 4) {
                float4 sv0 = *reinterpret_cast<const float4*>(s0 + k);
                float4 sv1 = *reinterpret_cast<const float4*>(s1 + k);
                float4 sv2 = *reinterpret_cast<const float4*>(s2 + k);
                float4 qv0 = *reinterpret_cast<const float4*>(q0 + k);
                float4 qv1 = *reinterpret_cast<const float4*>(q1 + k);
                float4 qv2 = *reinterpret_cast<const float4*>(q2 + k);
                a00 = fmaf(sv0.x, qv0.x, a00); a00 = fmaf(sv0.y, qv0.y, a00);
                a00 = fmaf(sv0.z, qv0.z, a00); a00 = fmaf(sv0.w, qv0.w, a00);
                a01 = fmaf(sv0.x, qv1.x, a01); a01 = fmaf(sv0.y, qv1.y, a01);
                a01 = fmaf(sv0.z, qv1.z, a01); a01 = fmaf(sv0.w, qv1.w, a01);
                a02 = fmaf(sv0.x, qv2.x, a02); a02 = fmaf(sv0.y, qv2.y, a02);
                a02 = fmaf(sv0.z, qv2.z, a02); a02 = fmaf(sv0.w, qv2.w, a02);
                a10 = fmaf(sv1.x, qv0.x, a10); a10 = fmaf(sv1.y, qv0.y, a10);
                a10 = fmaf(sv1.z, qv0.z, a10); a10 = fmaf(sv1.w, qv0.w, a10);
                a11 = fmaf(sv1.x, qv1.x, a11); a11 = fmaf(sv1.y, qv1.y, a11);
                a11 = fmaf(sv1.z, qv1.z, a11); a11 = fmaf(sv1.w, qv1.w, a11);
                a12 = fmaf(sv1.x, qv2.x, a12); a12 = fmaf(sv1.y, qv2.y, a12);
                a12 = fmaf(sv1.z, qv2.z, a12); a12 = fmaf(sv1.w, qv2.w, a12);
                a20 = fmaf(sv2.x, qv0.x, a20); a20 = fmaf(sv2.y, qv0.y, a20);
                a20 = fmaf(sv2.z, qv0.z, a20); a20 = fmaf(sv2.w, qv0.w, a20);
                a21 = fmaf(sv2.x, qv1.x, a21); a21 = fmaf(sv2.y, qv1.y, a21);
                a21 = fmaf(sv2.z, qv1.z, a21); a21 = fmaf(sv2.w, qv1.w, a21);
                a22 = fmaf(sv2.x, qv2.x, a22); a22 = fmaf(sv2.y, qv2.y, a22);
                a22 = fmaf(sv2.z, qv2.z, a22); a22 = fmaf(sv2.w, qv2.w, a22);
            }
            float* pr = psum[t];
            pr[0] = a00; pr[1] = a01; pr[2] = a02;
            pr[3] = a10; pr[4] = a11; pr[5] = a12;
            pr[6] = a20; pr[7] = a21; pr[8] = a22;
        }
        __syncthreads();
        if (t < 81) {
            int h = t / 9, wq = t % 9;
            int tile = (h / 3) * 3 + wq / 3;
            int e = (h % 3) * 3 + (wq % 3);
            float s = 0.f;
#pragma unroll
            for (int k = 0; k < 16; k++) s += psum[tile * 16 + k][e];
            simm[t] = s;
        }
        __syncthreads();

        if (t < 32) {
            float v0 = simm[t];
            float v1 = simm[t + 32];
            float v2 = (t + 64 < 81) ? simm[t + 64] : -1e30f;
            unsigned rmask = 0x1FFu, cmask = 0x1FFu;
            float totalv = 0.f, beta = 1.f;
            for (int it = 0; it < 9; it++) {
                float bv = -1e30f;
                int bidx = 999;
                int j = t;
                if (((rmask >> (j / 9)) & 1) && ((cmask >> (j % 9)) & 1)) {
                    bv = v0; bidx = j;
                }
                j = t + 32;
                if (((rmask >> (j / 9)) & 1) && ((cmask >> (j % 9)) & 1)) {
                    if (v1 > bv || (v1 == bv && j < bidx)) { bv = v1; bidx = j; }
                }
                j = t + 64;
                if (j < 81 && ((rmask >> (j / 9)) & 1) && ((cmask >> (j % 9)) & 1)) {
                    if (v2 > bv || (v2 == bv && j < bidx)) { bv = v2; bidx = j; }
                }
#pragma unroll
                for (int off = 16; off; off >>= 1) {
                    float ov = __shfl_xor_sync(0xffffffffu, bv, off);
                    int   oi = __shfl_xor_sync(0xffffffffu, bidx, off);
                    if (ov > bv || (ov == bv && oi < bidx)) { bv = ov; bidx = oi; }
                }
                totalv = fmaf(fmaxf(bv, 0.f), beta, totalv);
                beta *= 0.5f;
                rmask &= ~(1u << (bidx / 9));
                cmask &= ~(1u << (bidx % 9));
            }
            if (t == 0) out[((size_t)b * NQ_ + n) * WAY_ + m] = totalv;
        }
    }
}

// ---------------------------------------------------------------------------
extern "C" void kernel_launch(void* const* d_in, const int* in_sizes, int n_in,
                              void* d_out, int out_size) {
    const float* data   = (const float*)d_in[0];
    const float* conv_w = (const float*)d_in[1];
    (void)in_sizes; (void)n_in; (void)out_size;

    static bool attr_set = false;
    if (!attr_set) {
        cudaFuncSetAttribute(k_gemm, cudaFuncAttributeMaxDynamicSharedMemorySize, SMT);
        attr_set = true;
    }

    k_prepw<<<(CO * KD + 255) / 256, 256>>>(conv_w);
    k_prepx<<<NS, 128>>>(data);
    k_gemm<<<NTOT / TNB, 640, SMT>>>();
    k_sim<<<B_ * NQ_, 160>>>((float*)d_out);
}

// round 10
// speedup vs baseline: 1.3879x; 1.0095x over previous
#include <cuda_runtime.h>
#include <cuda_fp16.h>
#include <cstdint>
#include <math.h>

// ---------------- problem constants ----------------
#define NS   5760
#define CO   640
#define KD   192
#define NPOS 16
#define B_   8
#define WAY_ 5
#define NQ_  75
#define P_   9
#define NTOT (NS * NPOS)     // 92160
#define KE2  576             // 3 * 192 fp16-split K
#define TNB  64              // N per block = 4 images
#define KC   48              // K halves per chunk
#define NCH  12              // 576 / 48

// ---------------- device scratch ----------------
__device__ __align__(128) __half g_W[(size_t)CO * KE2];    // 737 KB
__device__ float g_u[(size_t)NS * CO];

__device__ __forceinline__ uint32_t smem_u32(const void* p) {
    uint32_t a;
    asm("{ .reg .u64 t; cvta.to.shared.u64 t, %1; cvt.u32.u64 %0, t; }"
        : "=r"(a) : "l"(p));
    return a;
}

// ---------------------------------------------------------------------------
// Prep W: fp16 split, K-concat [w0 | w0 | w1]
// ---------------------------------------------------------------------------
__global__ void k_prepw(const float* __restrict__ w) {
    int i = blockIdx.x * 256 + threadIdx.x;
    if (i >= CO * KD) return;
    int ch = i / KD, k = i % KD;
    float v = w[i];
    __half h0 = __float2half_rn(v);
    __half h1 = __float2half_rn(v - __half2float(h0));
    size_t b = (size_t)ch * KE2;
    g_W[b + k]       = h0;
    g_W[b + 192 + k] = h0;
    g_W[b + 384 + k] = h1;
}

// ---------------------------------------------------------------------------
// Fused im2col + GEMM + norms. B staged directly from raw images (no g_X).
// A staged per-warp (warp-private rows), double-buffered, no block sync in
// the mainloop.
// ---------------------------------------------------------------------------
#define BST      584                      // B row stride (halves): 1168 B
#define AST      56                       // A row stride (halves): 112 B
#define OFF_B    0
#define BSZ      (64 * BST * 2)           // 74752
#define OFF_A    BSZ
#define ABUF_SZ  (32 * AST * 2)           // 3584 per warp-buffer
#define AWARP_SZ (2 * ABUF_SZ)            // 7168 per warp
#define SMT      (OFF_A + 20 * AWARP_SZ)  // 218112
#define OFF_SSQ  OFF_A
#define OFF_SS2  (OFF_A + 256)
#define OFF_VSM  (OFF_A + 272)

#define LDSM4(r0, r1, r2, r3, ad) \
    asm volatile("ldmatrix.sync.aligned.m8n8.x4.shared.b16 {%0,%1,%2,%3},[%4];" \
                 : "=r"(r0), "=r"(r1), "=r"(r2), "=r"(r3) : "r"(ad))

__global__ void __launch_bounds__(640, 1) k_gemm(const float* __restrict__ data) {
    extern __shared__ char sm[];
    const int t = threadIdx.x, w = t >> 5, lane = t & 31;
    const int bid = blockIdx.x;
    const uint32_t sb = smem_u32(sm);
    const uint32_t aWarpBase = sb + OFF_A + w * AWARP_SZ;

    // --- per-warp A chunk: 32 rows x 96 B, 6 x 16B per lane ---
    auto issueA = [&](int c, int buf) {
        const int kc = KC * c;
#pragma unroll
        for (int i = 0; i < 6; i++) {
            int g = lane + 32 * i;
            int row = g / 6, part = g % 6;
            const __half* src = g_W + (size_t)(w * 32 + row) * KE2 + kc + part * 8;
            uint32_t dst = aWarpBase + buf * ABUF_SZ + row * (AST * 2) + part * 16;
            asm volatile("cp.async.cg.shared.global [%0], [%1], 16;"
                         :: "r"(dst), "l"(src));
        }
        asm volatile("cp.async.commit_group;");
    };
    issueA(0, 0);
    issueA(1, 1);

    // --- stage B: im2col + fp16 split straight from raw images ---
    // 4 images x 3072 floats -> B rows (j*16+pos), halves [x0|x1|x0]
    const float* imgs = data + (size_t)bid * 4 * 3072;
    for (int g = t; g < 4 * 3072; g += 640) {
        int j = g / 3072, i = g - j * 3072;
        float v = imgs[g];
        int ci = i >> 10, rem = i & 1023;
        int row = rem >> 5, col = rem & 31;
        int k   = ci * 64 + (row & 7) * 8 + (col & 7);
        int pos = (row >> 3) * 4 + (col >> 3);
        __half h0 = __float2half_rn(v);
        __half h1 = __float2half_rn(v - __half2float(h0));
        char* rb = sm + OFF_B + (j * 16 + pos) * (BST * 2);
        *reinterpret_cast<__half*>(rb + 2 * k)         = h0;
        *reinterpret_cast<__half*>(rb + 2 * (192 + k)) = h1;
        *reinterpret_cast<__half*>(rb + 2 * (384 + k)) = h0;
    }
    __syncthreads();   // ONLY block-wide sync before epilogue

    float acc[2][8][4];
#pragma unroll
    for (int mt = 0; mt < 2; mt++)
#pragma unroll
        for (int nt = 0; nt < 8; nt++)
#pragma unroll
            for (int c = 0; c < 4; c++) acc[mt][nt][c] = 0.f;

    const int lm = lane >> 3;
    const uint32_t aAddr = aWarpBase +
        (((lm & 1) * 8 + (lane & 7)) * AST + (lm >> 1) * 8) * 2;
    const uint32_t bAddr = sb + OFF_B +
        (((lm >> 1) * 8 + (lane & 7)) * BST + (lm & 1) * 8) * 2;

    for (int c = 0; c < NCH; c++) {
        if (c + 1 < NCH) asm volatile("cp.async.wait_group 1;");
        else             asm volatile("cp.async.wait_group 0;");
        __syncwarp();

        const uint32_t aBuf = aAddr + (c & 1) * ABUF_SZ;
#pragma unroll
        for (int ks = 0; ks < 3; ks++) {
            uint32_t a0[4], a1[4];
            uint32_t aBase = aBuf + ks * 32;
            LDSM4(a0[0], a0[1], a0[2], a0[3], aBase);
            LDSM4(a1[0], a1[1], a1[2], a1[3], aBase + 16 * AST * 2);
#pragma unroll
            for (int ntp = 0; ntp < 4; ntp++) {
                uint32_t b[4];
                LDSM4(b[0], b[1], b[2], b[3],
                      bAddr + ntp * (16 * BST * 2) + c * (KC * 2) + ks * 32);
#pragma unroll
                for (int sub = 0; sub < 2; sub++) {
                    int nt = 2 * ntp + sub;
                    asm volatile(
                        "mma.sync.aligned.m16n8k16.row.col.f32.f16.f16.f32 "
                        "{%0,%1,%2,%3},{%4,%5,%6,%7},{%8,%9},{%0,%1,%2,%3};"
                        : "+f"(acc[0][nt][0]), "+f"(acc[0][nt][1]),
                          "+f"(acc[0][nt][2]), "+f"(acc[0][nt][3])
                        : "r"(a0[0]), "r"(a0[1]), "r"(a0[2]), "r"(a0[3]),
                          "r"(b[2 * sub]), "r"(b[2 * sub + 1]));
                    asm volatile(
                        "mma.sync.aligned.m16n8k16.row.col.f32.f16.f16.f32 "
                        "{%0,%1,%2,%3},{%4,%5,%6,%7},{%8,%9},{%0,%1,%2,%3};"
                        : "+f"(acc[1][nt][0]), "+f"(acc[1][nt][1]),
                          "+f"(acc[1][nt][2]), "+f"(acc[1][nt][3])
                        : "r"(a1[0]), "r"(a1[1]), "r"(a1[2]), "r"(a1[3]),
                          "r"(b[2 * sub]), "r"(b[2 * sub + 1]));
                }
            }
        }
        if (c + 2 < NCH) issueA(c + 2, c & 1);   // buffer of c now free
    }
    __syncthreads();   // all warps done; A region reusable as scratch

    float* ssq = reinterpret_cast<float*>(sm + OFF_SSQ);
    float* ss2 = reinterpret_cast<float*>(sm + OFF_SS2);
    float* vsm = reinterpret_cast<float*>(sm + OFF_VSM);
    if (t < 64) ssq[t] = 0.f;
    if (t >= 64 && t < 68) ss2[t - 64] = 0.f;
    __syncthreads();

    // ---- epilogue: per-position channel L2-norm ----
    {
        float cs[16];
#pragma unroll
        for (int nt = 0; nt < 8; nt++)
#pragma unroll
            for (int par = 0; par < 2; par++) {
                float s = 0.f;
#pragma unroll
                for (int mt = 0; mt < 2; mt++) {
                    float x0 = acc[mt][nt][par], x1 = acc[mt][nt][2 + par];
                    s = fmaf(x0, x0, s);
                    s = fmaf(x1, x1, s);
                }
                cs[nt * 2 + par] = s;
            }
#pragma unroll
        for (int i = 0; i < 16; i++) {
            cs[i] += __shfl_xor_sync(0xffffffffu, cs[i], 4);
            cs[i] += __shfl_xor_sync(0xffffffffu, cs[i], 8);
            cs[i] += __shfl_xor_sync(0xffffffffu, cs[i], 16);
        }
        if (lane < 4) {
#pragma unroll
            for (int nt = 0; nt < 8; nt++)
#pragma unroll
                for (int par = 0; par < 2; par++)
                    atomicAdd(&ssq[nt * 8 + lane * 2 + par], cs[nt * 2 + par]);
        }
    }
    __syncthreads();
    if (t < 64) ssq[t] = 1.f / fmaxf(sqrtf(ssq[t]), 1e-12f);
    __syncthreads();

    // ---- pool over positions + final channel L2-norm ----
    float sq[4] = {0.f, 0.f, 0.f, 0.f};
#pragma unroll
    for (int mt = 0; mt < 2; mt++)
#pragma unroll
        for (int h = 0; h < 2; h++)
#pragma unroll
            for (int j = 0; j < 4; j++) {
                float s = 0.f;
#pragma unroll
                for (int ntl = 0; ntl < 2; ntl++) {
                    int nt = 2 * j + ntl;
#pragma unroll
                    for (int par = 0; par < 2; par++) {
                        int col = nt * 8 + (lane & 3) * 2 + par;
                        s = fmaf(acc[mt][nt][h * 2 + par], ssq[col], s);
                    }
                }
                s += __shfl_xor_sync(0xffffffffu, s, 1);
                s += __shfl_xor_sync(0xffffffffu, s, 2);
                if ((lane & 3) == 0) {
                    int row = w * 32 + mt * 16 + h * 8 + (lane >> 2);
                    float v = s * 0.0625f;
                    vsm[row * 4 + j] = v;
                    sq[j] = fmaf(v, v, sq[j]);
                }
            }
#pragma unroll
    for (int j = 0; j < 4; j++) {
        sq[j] += __shfl_xor_sync(0xffffffffu, sq[j], 4);
        sq[j] += __shfl_xor_sync(0xffffffffu, sq[j], 8);
        sq[j] += __shfl_xor_sync(0xffffffffu, sq[j], 16);
    }
    if (lane == 0)
#pragma unroll
        for (int j = 0; j < 4; j++) atomicAdd(&ss2[j], sq[j]);
    __syncthreads();
    if (t < 4) ss2[t] = 1.f / fmaxf(sqrtf(ss2[t]), 1e-12f);
    __syncthreads();

    for (int g = t; g < 2560; g += 640) {
        int ch = g >> 2, j = g & 3;
        g_u[(size_t)(4 * bid + j) * CO + ch] = vsm[ch * 4 + j] * ss2[j];
    }
}

// ---------------------------------------------------------------------------
// Sim + greedy. Register-tiled 3x3 (R8, 47 µs) — unchanged.
// ---------------------------------------------------------------------------
#define QSTRIDE 644

__global__ void __launch_bounds__(160) k_sim(float* __restrict__ out) {
    __shared__ float qsm[9 * QSTRIDE];
    __shared__ float ssm[9 * QSTRIDE];
    __shared__ float psum[144][9];
    __shared__ float simm[81];

    const int b = blockIdx.x / NQ_;
    const int n = blockIdx.x % NQ_;
    const int t = threadIdx.x;

    const float* qb = g_u + ((size_t)(b * 80 + WAY_ + n) * P_) * CO;
    for (int i = t; i < 9 * 160; i += 160) {
        int r = i / 160, c4 = (i % 160) * 4;
        *reinterpret_cast<float4*>(&qsm[r * QSTRIDE + c4]) =
            *reinterpret_cast<const float4*>(qb + (size_t)r * CO + c4);
    }

    const int tt = t >> 4;
    const int ss = t & 15;
    const int h0 = (tt / 3) * 3;
    const int w0 = (tt % 3) * 3;
    const int k0 = ss * 40;

    for (int m = 0; m < WAY_; m++) {
        const float* sbp = g_u + ((size_t)(b * 80 + m) * P_) * CO;
        __syncthreads();
        for (int i = t; i < 9 * 160; i += 160) {
            int r = i / 160, c4 = (i % 160) * 4;
            *reinterpret_cast<float4*>(&ssm[r * QSTRIDE + c4]) =
                *reinterpret_cast<const float4*>(sbp + (size_t)r * CO + c4);
        }
        __syncthreads();

        if (t < 144) {
            float a00 = 0.f, a01 = 0.f, a02 = 0.f;
            float a10 = 0.f, a11 = 0.f, a12 = 0.f;
            float a20 = 0.f, a21 = 0.f, a22 = 0.f;
            const float* s0 = &ssm[(h0 + 0) * QSTRIDE + k0];
            const float* s1 = &ssm[(h0 + 1) * QSTRIDE + k0];
            const float* s2 = &ssm[(h0 + 2) * QSTRIDE + k0];
            const float* q0 = &qsm[(w0 + 0) * QSTRIDE + k0];
            const float* q1 = &qsm[(w0 + 1) * QSTRIDE + k0];
            const float* q2 = &qsm[(w0 + 2) * QSTRIDE + k0];
#pragma unroll 2
            for (int k = 0; k < 40; k += 4) {
                float4 sv0 = *reinterpret_cast<const float4*>(s0 + k);
                float4 sv1 = *reinterpret_cast<const float4*>(s1 + k);
                float4 sv2 = *reinterpret_cast<const float4*>(s2 + k);
                float4 qv0 = *reinterpret_cast<const float4*>(q0 + k);
                float4 qv1 = *reinterpret_cast<const float4*>(q1 + k);
                float4 qv2 = *reinterpret_cast<const float4*>(q2 + k);
                a00 = fmaf(sv0.x, qv0.x, a00); a00 = fmaf(sv0.y, qv0.y, a00);
                a00 = fmaf(sv0.z, qv0.z, a00); a00 = fmaf(sv0.w, qv0.w, a00);
                a01 = fmaf(sv0.x, qv1.x, a01); a01 = fmaf(sv0.y, qv1.y, a01);
                a01 = fmaf(sv0.z, qv1.z, a01); a01 = fmaf(sv0.w, qv1.w, a01);
                a02 = fmaf(sv0.x, qv2.x, a02); a02 = fmaf(sv0.y, qv2.y, a02);
                a02 = fmaf(sv0.z, qv2.z, a02); a02 = fmaf(sv0.w, qv2.w, a02);
                a10 = fmaf(sv1.x, qv0.x, a10); a10 = fmaf(sv1.y, qv0.y, a10);
                a10 = fmaf(sv1.z, qv0.z, a10); a10 = fmaf(sv1.w, qv0.w, a10);
                a11 = fmaf(sv1.x, qv1.x, a11); a11 = fmaf(sv1.y, qv1.y, a11);
                a11 = fmaf(sv1.z, qv1.z, a11); a11 = fmaf(sv1.w, qv1.w, a11);
                a12 = fmaf(sv1.x, qv2.x, a12); a12 = fmaf(sv1.y, qv2.y, a12);
                a12 = fmaf(sv1.z, qv2.z, a12); a12 = fmaf(sv1.w, qv2.w, a12);
                a20 = fmaf(sv2.x, qv0.x, a20); a20 = fmaf(sv2.y, qv0.y, a20);
                a20 = fmaf(sv2.z, qv0.z, a20); a20 = fmaf(sv2.w, qv0.w, a20);
                a21 = fmaf(sv2.x, qv1.x, a21); a21 = fmaf(sv2.y, qv1.y, a21);
                a21 = fmaf(sv2.z, qv1.z, a21); a21 = fmaf(sv2.w, qv1.w, a21);
                a22 = fmaf(sv2.x, qv2.x, a22); a22 = fmaf(sv2.y, qv2.y, a22);
                a22 = fmaf(sv2.z, qv2.z, a22); a22 = fmaf(sv2.w, qv2.w, a22);
            }
            float* pr = psum[t];
            pr[0] = a00; pr[1] = a01; pr[2] = a02;
            pr[3] = a10; pr[4] = a11; pr[5] = a12;
            pr[6] = a20; pr[7] = a21; pr[8] = a22;
        }
        __syncthreads();
        if (t < 81) {
            int h = t / 9, wq = t % 9;
            int tile = (h / 3) * 3 + wq / 3;
            int e = (h % 3) * 3 + (wq % 3);
            float s = 0.f;
#pragma unroll
            for (int k = 0; k < 16; k++) s += psum[tile * 16 + k][e];
            simm[t] = s;
        }
        __syncthreads();

        if (t < 32) {
            float v0 = simm[t];
            float v1 = simm[t + 32];
            float v2 = (t + 64 < 81) ? simm[t + 64] : -1e30f;
            unsigned rmask = 0x1FFu, cmask = 0x1FFu;
            float totalv = 0.f, beta = 1.f;
            for (int it = 0; it < 9; it++) {
                float bv = -1e30f;
                int bidx = 999;
                int j = t;
                if (((rmask >> (j / 9)) & 1) && ((cmask >> (j % 9)) & 1)) {
                    bv = v0; bidx = j;
                }
                j = t + 32;
                if (((rmask >> (j / 9)) & 1) && ((cmask >> (j % 9)) & 1)) {
                    if (v1 > bv || (v1 == bv && j < bidx)) { bv = v1; bidx = j; }
                }
                j = t + 64;
                if (j < 81 && ((rmask >> (j / 9)) & 1) && ((cmask >> (j % 9)) & 1)) {
                    if (v2 > bv || (v2 == bv && j < bidx)) { bv = v2; bidx = j; }
                }
#pragma unroll
                for (int off = 16; off; off >>= 1) {
                    float ov = __shfl_xor_sync(0xffffffffu, bv, off);
                    int   oi = __shfl_xor_sync(0xffffffffu, bidx, off);
                    if (ov > bv || (ov == bv && oi < bidx)) { bv = ov; bidx = oi; }
                }
                totalv = fmaf(fmaxf(bv, 0.f), beta, totalv);
                beta *= 0.5f;
                rmask &= ~(1u << (bidx / 9));
                cmask &= ~(1u << (bidx % 9));
            }
            if (t == 0) out[((size_t)b * NQ_ + n) * WAY_ + m] = totalv;
        }
    }
}

// ---------------------------------------------------------------------------
extern "C" void kernel_launch(void* const* d_in, const int* in_sizes, int n_in,
                              void* d_out, int out_size) {
    const float* data   = (const float*)d_in[0];
    const float* conv_w = (const float*)d_in[1];
    (void)in_sizes; (void)n_in; (void)out_size;

    static bool attr_set = false;
    if (!attr_set) {
        cudaFuncSetAttribute(k_gemm, cudaFuncAttributeMaxDynamicSharedMemorySize, SMT);
        attr_set = true;
    }

    k_prepw<<<(CO * KD + 255) / 256, 256>>>(conv_w);
    k_gemm<<<NTOT / TNB, 640, SMT>>>(data);
    k_sim<<<B_ * NQ_, 160>>>((float*)d_out);
}

// round 12
// speedup vs baseline: 1.6003x; 1.1530x over previous
#include <cuda_runtime.h>
#include <cuda_fp16.h>
#include <cstdint>
#include <math.h>

// ---------------- problem constants ----------------
#define NS   5760
#define CO   640
#define KD   192
#define NPOS 16
#define B_   8
#define WAY_ 5
#define NQ_  75
#define P_   9
#define NTOT (NS * NPOS)     // 92160
#define KE2  576             // 3 * 192 fp16-split K
#define TNB  64              // N per block = 4 images
#define KC   32              // K halves per chunk
#define NCH  18              // 576 / 32

// ---------------- device scratch ----------------
__device__ __align__(128) __half g_W[(size_t)CO * KE2];    // 737 KB
__device__ float g_u[(size_t)NS * CO];

__device__ __forceinline__ uint32_t smem_u32(const void* p) {
    uint32_t a;
    asm("{ .reg .u64 t; cvta.to.shared.u64 t, %1; cvt.u32.u64 %0, t; }"
        : "=r"(a) : "l"(p));
    return a;
}

// ---------------------------------------------------------------------------
// Prep W: fp16 split, K-concat [w0 | w0 | w1]
// ---------------------------------------------------------------------------
__global__ void k_prepw(const float* __restrict__ w) {
    int i = blockIdx.x * 256 + threadIdx.x;
    if (i >= CO * KD) return;
    int ch = i / KD, k = i % KD;
    float v = w[i];
    __half h0 = __float2half_rn(v);
    __half h1 = __float2half_rn(v - __half2float(h0));
    size_t b = (size_t)ch * KE2;
    g_W[b + k]       = h0;
    g_W[b + 192 + k] = h0;
    g_W[b + 384 + k] = h1;
}

// ---------------------------------------------------------------------------
// Fused im2col + GEMM + norms. Vectorized B scatter (16B stores); per-warp
// triple-buffered A (R9 mainloop); no block sync in the mainloop.
// ---------------------------------------------------------------------------
#define BST      584                      // B row stride (halves): 1168 B
#define AST      40                       // A row stride (halves): 80 B
#define OFF_B    0
#define BSZ      (64 * BST * 2)           // 74752
#define OFF_A    BSZ
#define ABUF_SZ  (32 * AST * 2)           // 2560 per warp-buffer
#define AWARP_SZ (3 * ABUF_SZ)            // 7680 per warp
#define SMT      (OFF_A + 20 * AWARP_SZ)  // 228352
#define OFF_SSQ  OFF_A
#define OFF_SS2  (OFF_A + 256)
#define OFF_VSM  (OFF_A + 272)

#define LDSM4(r0, r1, r2, r3, ad) \
    asm volatile("ldmatrix.sync.aligned.m8n8.x4.shared.b16 {%0,%1,%2,%3},[%4];" \
                 : "=r"(r0), "=r"(r1), "=r"(r2), "=r"(r3) : "r"(ad))

__global__ void __launch_bounds__(640, 1) k_gemm(const float* __restrict__ data) {
    extern __shared__ char sm[];
    const int t = threadIdx.x, w = t >> 5, lane = t & 31;
    const int bid = blockIdx.x;
    const uint32_t sb = smem_u32(sm);
    const uint32_t aWarpBase = sb + OFF_A + w * AWARP_SZ;

    // --- per-warp A chunk: 32 rows x 64 B, 4 x 16B per lane ---
    auto issueA = [&](int c, int buf) {
        const int kc = KC * c;
#pragma unroll
        for (int i = 0; i < 4; i++) {
            int g = lane + 32 * i;
            int row = g >> 2, part = g & 3;
            const __half* src = g_W + (size_t)(w * 32 + row) * KE2 + kc + part * 8;
            uint32_t dst = aWarpBase + buf * ABUF_SZ + row * (AST * 2) + part * 16;
            asm volatile("cp.async.cg.shared.global [%0], [%1], 16;"
                         :: "r"(dst), "l"(src));
        }
        asm volatile("cp.async.commit_group;");
    };
    issueA(0, 0);
    issueA(1, 1);

    // --- stage B: im2col + fp16 split, vectorized 8 pixels / 16B stores ---
    const float* imgs = data + (size_t)bid * 4 * 3072;
    for (int g = t; g < 1536; g += 640) {
        int j = g / 384, rem = g - j * 384;
        int base = rem * 8;                    // 8 row-contiguous pixels
        int ci = base >> 10, r2 = base & 1023;
        int row = r2 >> 5, cb = r2 & 31;       // cb in {0,8,16,24}
        int kb  = ci * 64 + (row & 7) * 8;     // k run start (col&7 = 0..7)
        int pos = (row >> 3) * 4 + (cb >> 3);
        const float* p = imgs + j * 3072 + base;
        float4 va = *reinterpret_cast<const float4*>(p);
        float4 vb = *reinterpret_cast<const float4*>(p + 4);
        float vv[8] = {va.x, va.y, va.z, va.w, vb.x, vb.y, vb.z, vb.w};
        union { __half2 h2[4]; uint4 u; } t0, t1;
#pragma unroll
        for (int i = 0; i < 4; i++) {
            __half a0 = __float2half_rn(vv[2 * i]);
            __half b0 = __float2half_rn(vv[2 * i + 1]);
            __half a1 = __float2half_rn(vv[2 * i]     - __half2float(a0));
            __half b1 = __float2half_rn(vv[2 * i + 1] - __half2float(b0));
            t0.h2[i] = __halves2half2(a0, b0);
            t1.h2[i] = __halves2half2(a1, b1);
        }
        char* rb = sm + OFF_B + (j * 16 + pos) * (BST * 2);
        *reinterpret_cast<uint4*>(rb + 2 * kb)         = t0.u;
        *reinterpret_cast<uint4*>(rb + 2 * (192 + kb)) = t1.u;
        *reinterpret_cast<uint4*>(rb + 2 * (384 + kb)) = t0.u;
    }
    __syncthreads();   // ONLY block-wide sync before epilogue

    float acc[2][8][4];
#pragma unroll
    for (int mt = 0; mt < 2; mt++)
#pragma unroll
        for (int nt = 0; nt < 8; nt++)
#pragma unroll
            for (int c = 0; c < 4; c++) acc[mt][nt][c] = 0.f;

    const int lm = lane >> 3;
    const uint32_t aAddr = aWarpBase +
        (((lm & 1) * 8 + (lane & 7)) * AST + (lm >> 1) * 8) * 2;
    const uint32_t bAddr = sb + OFF_B +
        (((lm >> 1) * 8 + (lane & 7)) * BST + (lm & 1) * 8) * 2;

    for (int c = 0; c < NCH; c++) {
        if (c + 1 < NCH) asm volatile("cp.async.wait_group 1;");
        else             asm volatile("cp.async.wait_group 0;");
        __syncwarp();
        if (c + 2 < NCH) issueA(c + 2, (c + 2) % 3);

        const uint32_t aBuf = aAddr + (c % 3) * ABUF_SZ;
#pragma unroll
        for (int ks = 0; ks < 2; ks++) {
            uint32_t a0[4], a1[4];
            uint32_t aBase = aBuf + ks * 32;
            LDSM4(a0[0], a0[1], a0[2], a0[3], aBase);
            LDSM4(a1[0], a1[1], a1[2], a1[3], aBase + 16 * AST * 2);
#pragma unroll
            for (int ntp = 0; ntp < 4; ntp++) {
                uint32_t b[4];
                LDSM4(b[0], b[1], b[2], b[3],
                      bAddr + ntp * (16 * BST * 2) + c * (KC * 2) + ks * 32);
#pragma unroll
                for (int sub = 0; sub < 2; sub++) {
                    int nt = 2 * ntp + sub;
                    asm volatile(
                        "mma.sync.aligned.m16n8k16.row.col.f32.f16.f16.f32 "
                        "{%0,%1,%2,%3},{%4,%5,%6,%7},{%8,%9},{%0,%1,%2,%3};"
                        : "+f"(acc[0][nt][0]), "+f"(acc[0][nt][1]),
                          "+f"(acc[0][nt][2]), "+f"(acc[0][nt][3])
                        : "r"(a0[0]), "r"(a0[1]), "r"(a0[2]), "r"(a0[3]),
                          "r"(b[2 * sub]), "r"(b[2 * sub + 1]));
                    asm volatile(
                        "mma.sync.aligned.m16n8k16.row.col.f32.f16.f16.f32 "
                        "{%0,%1,%2,%3},{%4,%5,%6,%7},{%8,%9},{%0,%1,%2,%3};"
                        : "+f"(acc[1][nt][0]), "+f"(acc[1][nt][1]),
                          "+f"(acc[1][nt][2]), "+f"(acc[1][nt][3])
                        : "r"(a1[0]), "r"(a1[1]), "r"(a1[2]), "r"(a1[3]),
                          "r"(b[2 * sub]), "r"(b[2 * sub + 1]));
                }
            }
        }
    }
    __syncthreads();   // all warps done; A region reusable as scratch

    float* ssq = reinterpret_cast<float*>(sm + OFF_SSQ);
    float* ss2 = reinterpret_cast<float*>(sm + OFF_SS2);
    float* vsm = reinterpret_cast<float*>(sm + OFF_VSM);
    if (t < 64) ssq[t] = 0.f;
    if (t >= 64 && t < 68) ss2[t - 64] = 0.f;
    __syncthreads();

    // ---- epilogue: per-position channel L2-norm ----
    {
        float cs[16];
#pragma unroll
        for (int nt = 0; nt < 8; nt++)
#pragma unroll
            for (int par = 0; par < 2; par++) {
                float s = 0.f;
#pragma unroll
                for (int mt = 0; mt < 2; mt++) {
                    float x0 = acc[mt][nt][par], x1 = acc[mt][nt][2 + par];
                    s = fmaf(x0, x0, s);
                    s = fmaf(x1, x1, s);
                }
                cs[nt * 2 + par] = s;
            }
#pragma unroll
        for (int i = 0; i < 16; i++) {
            cs[i] += __shfl_xor_sync(0xffffffffu, cs[i], 4);
            cs[i] += __shfl_xor_sync(0xffffffffu, cs[i], 8);
            cs[i] += __shfl_xor_sync(0xffffffffu, cs[i], 16);
        }
        if (lane < 4) {
#pragma unroll
            for (int nt = 0; nt < 8; nt++)
#pragma unroll
                for (int par = 0; par < 2; par++)
                    atomicAdd(&ssq[nt * 8 + lane * 2 + par], cs[nt * 2 + par]);
        }
    }
    __syncthreads();
    if (t < 64) ssq[t] = 1.f / fmaxf(sqrtf(ssq[t]), 1e-12f);
    __syncthreads();

    // ---- pool over positions + final channel L2-norm ----
    float sq[4] = {0.f, 0.f, 0.f, 0.f};
#pragma unroll
    for (int mt = 0; mt < 2; mt++)
#pragma unroll
        for (int h = 0; h < 2; h++)
#pragma unroll
            for (int j = 0; j < 4; j++) {
                float s = 0.f;
#pragma unroll
                for (int ntl = 0; ntl < 2; ntl++) {
                    int nt = 2 * j + ntl;
#pragma unroll
                    for (int par = 0; par < 2; par++) {
                        int col = nt * 8 + (lane & 3) * 2 + par;
                        s = fmaf(acc[mt][nt][h * 2 + par], ssq[col], s);
                    }
                }
                s += __shfl_xor_sync(0xffffffffu, s, 1);
                s += __shfl_xor_sync(0xffffffffu, s, 2);
                if ((lane & 3) == 0) {
                    int row = w * 32 + mt * 16 + h * 8 + (lane >> 2);
                    float v = s * 0.0625f;
                    vsm[row * 4 + j] = v;
                    sq[j] = fmaf(v, v, sq[j]);
                }
            }
#pragma unroll
    for (int j = 0; j < 4; j++) {
        sq[j] += __shfl_xor_sync(0xffffffffu, sq[j], 4);
        sq[j] += __shfl_xor_sync(0xffffffffu, sq[j], 8);
        sq[j] += __shfl_xor_sync(0xffffffffu, sq[j], 16);
    }
    if (lane == 0)
#pragma unroll
        for (int j = 0; j < 4; j++) atomicAdd(&ss2[j], sq[j]);
    __syncthreads();
    if (t < 4) ss2[t] = 1.f / fmaxf(sqrtf(ss2[t]), 1e-12f);
    __syncthreads();

    for (int g = t; g < 2560; g += 640) {
        int ch = g >> 2, j = g & 3;
        g_u[(size_t)(4 * bid + j) * CO + ch] = vsm[ch * 4 + j] * ss2[j];
    }
}

// ---------------------------------------------------------------------------
// Sim + greedy, single-pass: block per (b,n), 384 threads, all 5 supports
// staged at once; psum over (m,tile,slice); 5 parallel greedy warps.
// ---------------------------------------------------------------------------
#define QS 644
#define SIMSMT ((54 * QS + 360 * 9 + 5 * 81) * 4)

__global__ void __launch_bounds__(384) k_sim(float* __restrict__ out) {
    extern __shared__ float smf[];
    float* rows = smf;                    // [54][QS]: 0..8 query, 9..53 support
    float* psum = smf + 54 * QS;          // [360][9]
    float* simm = psum + 360 * 9;         // [5][81]

    const int b = blockIdx.x / NQ_;
    const int n = blockIdx.x % NQ_;
    const int t = threadIdx.x;

    const float* qb = g_u + ((size_t)(b * 80 + WAY_ + n) * P_) * CO;
    const float* sb = g_u + ((size_t)(b * 80) * P_) * CO;   // 45 contiguous rows
    for (int i = t; i < 54 * 160; i += 384) {
        int r = i / 160, c4 = (i % 160) * 4;
        const float* src = (r < 9) ? qb + (size_t)r * CO + c4
                                   : sb + (size_t)(r - 9) * CO + c4;
        *reinterpret_cast<float4*>(&rows[r * QS + c4]) =
            *reinterpret_cast<const float4*>(src);
    }
    __syncthreads();

    if (t < 360) {
        const int m = t / 72, r = t % 72;
        const int tt = r >> 3, ss = r & 7;
        const int k0 = ss * 80;
        const float* s0 = &rows[(9 + m * 9 + (tt / 3) * 3 + 0) * QS + k0];
        const float* s1 = s0 + QS;
        const float* s2 = s1 + QS;
        const float* q0 = &rows[((tt % 3) * 3 + 0) * QS + k0];
        const float* q1 = q0 + QS;
        const float* q2 = q1 + QS;
        float a00 = 0.f, a01 = 0.f, a02 = 0.f;
        float a10 = 0.f, a11 = 0.f, a12 = 0.f;
        float a20 = 0.f, a21 = 0.f, a22 = 0.f;
#pragma unroll 2
        for (int k = 0; k < 80; k += 4) {
            float4 sv0 = *reinterpret_cast<const float4*>(s0 + k);
            float4 sv1 = *reinterpret_cast<const float4*>(s1 + k);
            float4 sv2 = *reinterpret_cast<const float4*>(s2 + k);
            float4 qv0 = *reinterpret_cast<const float4*>(q0 + k);
            float4 qv1 = *reinterpret_cast<const float4*>(q1 + k);
            float4 qv2 = *reinterpret_cast<const float4*>(q2 + k);
            a00 = fmaf(sv0.x, qv0.x, a00); a00 = fmaf(sv0.y, qv0.y, a00);
            a00 = fmaf(sv0.z, qv0.z, a00); a00 = fmaf(sv0.w, qv0.w, a00);
            a01 = fmaf(sv0.x, qv1.x, a01); a01 = fmaf(sv0.y, qv1.y, a01);
            a01 = fmaf(sv0.z, qv1.z, a01); a01 = fmaf(sv0.w, qv1.w, a01);
            a02 = fmaf(sv0.x, qv2.x, a02); a02 = fmaf(sv0.y, qv2.y, a02);
            a02 = fmaf(sv0.z, qv2.z, a02); a02 = fmaf(sv0.w, qv2.w, a02);
            a10 = fmaf(sv1.x, qv0.x, a10); a10 = fmaf(sv1.y, qv0.y, a10);
            a10 = fmaf(sv1.z, qv0.z, a10); a10 = fmaf(sv1.w, qv0.w, a10);
            a11 = fmaf(sv1.x, qv1.x, a11); a11 = fmaf(sv1.y, qv1.y, a11);
            a11 = fmaf(sv1.z, qv1.z, a11); a11 = fmaf(sv1.w, qv1.w, a11);
            a12 = fmaf(sv1.x, qv2.x, a12); a12 = fmaf(sv1.y, qv2.y, a12);
            a12 = fmaf(sv1.z, qv2.z, a12); a12 = fmaf(sv1.w, qv2.w, a12);
            a20 = fmaf(sv2.x, qv0.x, a20); a20 = fmaf(sv2.y, qv0.y, a20);
            a20 = fmaf(sv2.z, qv0.z, a20); a20 = fmaf(sv2.w, qv0.w, a20);
            a21 = fmaf(sv2.x, qv1.x, a21); a21 = fmaf(sv2.y, qv1.y, a21);
            a21 = fmaf(sv2.z, qv1.z, a21); a21 = fmaf(sv2.w, qv1.w, a21);
            a22 = fmaf(sv2.x, qv2.x, a22); a22 = fmaf(sv2.y, qv2.y, a22);
            a22 = fmaf(sv2.z, qv2.z, a22); a22 = fmaf(sv2.w, qv2.w, a22);
        }
        float* pr = &psum[t * 9];
        pr[0] = a00; pr[1] = a01; pr[2] = a02;
        pr[3] = a10; pr[4] = a11; pr[5] = a12;
        pr[6] = a20; pr[7] = a21; pr[8] = a22;
    }
    __syncthreads();

    // 405 outputs over 384 threads: grid-stride (fixes R11's t<405 bug)
    for (int i = t; i < 405; i += 384) {
        int m = i / 81, e = i % 81;
        int h = e / 9, wq = e % 9;
        int tile = (h / 3) * 3 + wq / 3;
        int el = (h % 3) * 3 + (wq % 3);
        float s = 0.f;
#pragma unroll
        for (int ss = 0; ss < 8; ss++)
            s += psum[(m * 72 + tile * 8 + ss) * 9 + el];
        simm[m * 81 + e] = s;
    }
    __syncthreads();

    // 5 greedy warps: warp m handles support m
    const int wp = t >> 5, lane = t & 31;
    if (wp < WAY_) {
        const float* sv = &simm[wp * 81];
        float v0 = sv[lane];
        float v1 = sv[lane + 32];
        float v2 = (lane + 64 < 81) ? sv[lane + 64] : -1e30f;
        unsigned rmask = 0x1FFu, cmask = 0x1FFu;
        float totalv = 0.f, beta = 1.f;
        for (int it = 0; it < 9; it++) {
            float bv = -1e30f;
            int bidx = 999;
            int j = lane;
            if (((rmask >> (j / 9)) & 1) && ((cmask >> (j % 9)) & 1)) {
                bv = v0; bidx = j;
            }
            j = lane + 32;
            if (((rmask >> (j / 9)) & 1) && ((cmask >> (j % 9)) & 1)) {
                if (v1 > bv || (v1 == bv && j < bidx)) { bv = v1; bidx = j; }
            }
            j = lane + 64;
            if (j < 81 && ((rmask >> (j / 9)) & 1) && ((cmask >> (j % 9)) & 1)) {
                if (v2 > bv || (v2 == bv && j < bidx)) { bv = v2; bidx = j; }
            }
#pragma unroll
            for (int off = 16; off; off >>= 1) {
                float ov = __shfl_xor_sync(0xffffffffu, bv, off);
                int   oi = __shfl_xor_sync(0xffffffffu, bidx, off);
                if (ov > bv || (ov == bv && oi < bidx)) { bv = ov; bidx = oi; }
            }
            totalv = fmaf(fmaxf(bv, 0.f), beta, totalv);
            beta *= 0.5f;
            rmask &= ~(1u << (bidx / 9));
            cmask &= ~(1u << (bidx % 9));
        }
        if (lane == 0) out[((size_t)b * NQ_ + n) * WAY_ + wp] = totalv;
    }
}

// ---------------------------------------------------------------------------
extern "C" void kernel_launch(void* const* d_in, const int* in_sizes, int n_in,
                              void* d_out, int out_size) {
    const float* data   = (const float*)d_in[0];
    const float* conv_w = (const float*)d_in[1];
    (void)in_sizes; (void)n_in; (void)out_size;

    static bool attr_set = false;
    if (!attr_set) {
        cudaFuncSetAttribute(k_gemm, cudaFuncAttributeMaxDynamicSharedMemorySize, SMT);
        cudaFuncSetAttribute(k_sim, cudaFuncAttributeMaxDynamicSharedMemorySize, SIMSMT);
        attr_set = true;
    }

    k_prepw<<<(CO * KD + 255) / 256, 256>>>(conv_w);
    k_gemm<<<NTOT / TNB, 640, SMT>>>(data);
    k_sim<<<B_ * NQ_, 384, SIMSMT>>>((float*)d_out);
}